// round 5
// baseline (speedup 1.0000x reference)
#include <cuda_runtime.h>
#include <cooperative_groups.h>
#include <cstdint>
#include <cstddef>

namespace cg = cooperative_groups;

#define BB      64
#define TIN     200
#define TOUT    400
#define DENC    512
#define DRNN    1024
#define PRE     256
#define ATT     128
#define KSZ     31
#define NMEL    80
#define GATESZ  4096
#define KSPLIT  8
#define NB      256
#define NT      256

// ---------------- device scratch ----------------
__device__ float d_xs[(size_t)TOUT * BB * PRE];
__device__ float d_pmT[(size_t)BB * ATT * TIN];   // [b][a][t]
__device__ float d_ah[BB * DRNN];
__device__ float d_ac[BB * DRNN];
__device__ float d_dh[BB * DRNN];
__device__ float d_dc[BB * DRNN];
__device__ float d_aw[BB * TIN];
__device__ float d_cum[BB * TIN];
__device__ float d_actx[BB * DENC];
__device__ float d_e[BB * TIN];
__device__ float d_gpart[(size_t)KSPLIT * GATESZ * BB];

// ---------------- fast math ----------------
__device__ __forceinline__ float tanh_fast(float x) {
    float ax = fabsf(x);
    float t  = __expf(-2.0f * ax);
    float r  = __fdividef(1.0f - t, 1.0f + t);
    return copysignf(r, x);
}
__device__ __forceinline__ float sig_fast(float x) {
    return __fdividef(1.0f, 1.0f + __expf(-x));
}

// ---------------- init (reset state every replay: determinism) ----------------
__global__ void init_state_kernel() {
    int i = blockIdx.x * 256 + threadIdx.x;
    int n = gridDim.x * 256;
    for (int k = i; k < BB * DRNN; k += n) { d_ah[k]=0.f; d_ac[k]=0.f; d_dh[k]=0.f; d_dc[k]=0.f; }
    for (int k = i; k < BB * TIN;  k += n) { d_aw[k]=0.f; d_cum[k]=0.f; }
    for (int k = i; k < BB * DENC; k += n) d_actx[k]=0.f;
}

// ---------------- prenet (all 400 steps, parallel) ----------------
__global__ void prenet_kernel(const float* __restrict__ dec_in,
                              const float* __restrict__ Wp1,
                              const float* __restrict__ Wp2) {
    __shared__ float di_s[32 * NMEL];
    __shared__ float h1_s[32 * PRE];
    int t = blockIdx.x, b0 = blockIdx.y * 32, tid = threadIdx.x;
    for (int i = tid; i < 32 * NMEL; i += 256) {
        int b = i / NMEL, k = i - b * NMEL;
        di_s[i] = (t == 0) ? 0.f : dec_in[((size_t)(t - 1) * BB + (b0 + b)) * NMEL + k];
    }
    __syncthreads();
    {
        const float* wr = Wp1 + tid * NMEL;
        for (int c = 0; c < 2; c++) {
            float acc[16];
            #pragma unroll
            for (int r = 0; r < 16; r++) acc[r] = 0.f;
            for (int k = 0; k < NMEL; k++) {
                float w = wr[k];
                #pragma unroll
                for (int r = 0; r < 16; r++)
                    acc[r] = fmaf(w, di_s[(c * 16 + r) * NMEL + k], acc[r]);
            }
            #pragma unroll
            for (int r = 0; r < 16; r++)
                h1_s[(c * 16 + r) * PRE + tid] = fmaxf(acc[r], 0.f);
        }
    }
    __syncthreads();
    {
        const float* wr = Wp2 + tid * PRE;
        for (int c = 0; c < 2; c++) {
            float acc[16];
            #pragma unroll
            for (int r = 0; r < 16; r++) acc[r] = 0.f;
            for (int k = 0; k < PRE; k++) {
                float w = wr[k];
                #pragma unroll
                for (int r = 0; r < 16; r++)
                    acc[r] = fmaf(w, h1_s[(c * 16 + r) * PRE + k], acc[r]);
            }
            #pragma unroll
            for (int r = 0; r < 16; r++)
                d_xs[((size_t)t * BB + (b0 + c * 16 + r)) * PRE + tid] = fmaxf(acc[r], 0.f);
        }
    }
}

// ---------------- processed memory, transposed: pmT[b][a][t] ----------------
__global__ void procmem_kernel(const float* __restrict__ enc,
                               const float* __restrict__ Wmem) {
    __shared__ float es[8 * DENC];
    int b = blockIdx.x, t0 = blockIdx.y * 8, tid = threadIdx.x;  // 128 threads
    for (int i = tid; i < 8 * DENC; i += 128)
        es[i] = enc[((size_t)b * TIN + t0) * DENC + i];
    __syncthreads();
    const float* wr = Wmem + tid * DENC;
    float acc[8];
    #pragma unroll
    for (int r = 0; r < 8; r++) acc[r] = 0.f;
    for (int e = 0; e < DENC; e++) {
        float w = wr[e];
        #pragma unroll
        for (int r = 0; r < 8; r++) acc[r] = fmaf(w, es[r * DENC + e], acc[r]);
    }
    #pragma unroll
    for (int r = 0; r < 8; r++)
        d_pmT[((size_t)b * ATT + tid) * TIN + t0 + r] = acc[r];
}

// ---------------- GEMM phase (device func, runs inside persistent kernel) ----------------
// gpart[split][m][b] = sum_k W[m][k] * x[b][k], tile 128(m) x 64(b), K-chunk 32
__device__ __forceinline__ void gemm_phase(
    float* pool, const float* __restrict__ Wih, int K1,
    const float* __restrict__ Whh,
    const float* __restrict__ x0, int L0,
    const float* __restrict__ x2,   // x1 is always d_actx (512)
    int Kq, int item) {
    float* Ws = pool;           // 32*132
    float* Xs = pool + 4224;    // 32*68
    const int tid = threadIdx.x;
    const int m0 = (item & 31) * 128;
    const int kstart = (item >> 5) * Kq;
    const int tr = tid >> 3, tb = tid & 7;
    const int L01 = L0 + DENC;
    float acc[4][8];
    #pragma unroll
    for (int i = 0; i < 4; i++)
        #pragma unroll
        for (int j = 0; j < 8; j++) acc[i][j] = 0.f;

    for (int kc = kstart; kc < kstart + Kq; kc += 32) {
        #pragma unroll
        for (int q = 0; q < 16; q++) {
            int idx = tid + q * 256, ml = idx >> 5, kl = idx & 31, kg = kc + kl;
            float w = (kg < K1) ? Wih[(size_t)(m0 + ml) * K1 + kg]
                                : Whh[(size_t)(m0 + ml) * 1024 + (kg - K1)];
            Ws[kl * 132 + ml] = w;
        }
        #pragma unroll
        for (int q = 0; q < 8; q++) {
            int idx = tid + q * 256, bl = idx >> 5, kl = idx & 31, kg = kc + kl;
            float xv;
            if (kg < L0)        xv = x0[bl * L0 + kg];
            else if (kg < L01)  xv = d_actx[bl * DENC + (kg - L0)];
            else                xv = x2[bl * 1024 + (kg - L01)];
            Xs[kl * 68 + bl] = xv;
        }
        __syncthreads();
        #pragma unroll
        for (int k = 0; k < 32; k++) {
            float4 w4 = *(const float4*)&Ws[k * 132 + tr * 4];
            float4 xa = *(const float4*)&Xs[k * 68 + tb * 8];
            float4 xb = *(const float4*)&Xs[k * 68 + tb * 8 + 4];
            float wv[4] = {w4.x, w4.y, w4.z, w4.w};
            float xv[8] = {xa.x, xa.y, xa.z, xa.w, xb.x, xb.y, xb.z, xb.w};
            #pragma unroll
            for (int i = 0; i < 4; i++)
                #pragma unroll
                for (int j = 0; j < 8; j++)
                    acc[i][j] = fmaf(wv[i], xv[j], acc[i][j]);
        }
        __syncthreads();
    }
    float* gp = d_gpart + (size_t)(item >> 5) * (GATESZ * BB);
    #pragma unroll
    for (int i = 0; i < 4; i++) {
        int m = m0 + tr * 4 + i;
        #pragma unroll
        for (int j = 0; j < 8; j++)
            gp[m * BB + tb * 8 + j] = acc[i][j];
    }
}

__device__ __forceinline__ void gates_phase(const float* __restrict__ bias,
                                            float* __restrict__ h, float* __restrict__ c) {
    int g = blockIdx.x * NT + threadIdx.x;   // exactly 65536
    int b = g & 63, j = g >> 6;
    float gi = bias[j], gf = bias[j + 1024], gg = bias[j + 2048], go = bias[j + 3072];
    #pragma unroll
    for (int s = 0; s < KSPLIT; s++) {
        const float* gp = d_gpart + (size_t)s * (GATESZ * BB);
        gi += gp[(j       ) * BB + b];
        gf += gp[(j + 1024) * BB + b];
        gg += gp[(j + 2048) * BB + b];
        go += gp[(j + 3072) * BB + b];
    }
    float cn = sig_fast(gf) * c[b * DRNN + j] + sig_fast(gi) * tanh_fast(gg);
    c[b * DRNN + j] = cn;
    h[b * DRNN + j] = sig_fast(go) * tanh_fast(cn);
}

// ---------------- persistent kernel ----------------
__global__ void __launch_bounds__(NT, 2)
persistent_kernel(const float* __restrict__ enc, const int* __restrict__ lens,
                  const float* __restrict__ Wih_a, const float* __restrict__ Whh_a,
                  const float* __restrict__ b_a,
                  const float* __restrict__ Wq, const float* __restrict__ Wconv,
                  const float* __restrict__ Wloc, const float* __restrict__ v,
                  const float* __restrict__ Wih_d, const float* __restrict__ Whh_d,
                  const float* __restrict__ b_d,
                  const float* __restrict__ Wp, const float* __restrict__ bp,
                  float* __restrict__ outs, float* __restrict__ aligns) {
    cg::grid_group grid = cg::this_grid();
    __shared__ __align__(16) float pool[6400];
    const int bid = blockIdx.x, tid = threadIdx.x;
    const int wid = tid >> 5, lane = tid & 31;

    for (int t = 0; t < TOUT; t++) {
        // ---- PA: attn GEMM (all 256 blocks) + out(t-1) on blocks < 64 ----
        gemm_phase(pool, Wih_a, 768, Whh_a,
                   d_xs + (size_t)t * BB * PRE, PRE, d_ah, 1792 / KSPLIT, bid);
        if (t > 0 && bid < BB) {
            __syncthreads();
            float* xin = pool;   // 1536
            for (int i = tid; i < 1024; i += NT) xin[i] = d_dh[bid * DRNN + i];
            for (int i = tid; i < 512;  i += NT) xin[1024 + i] = d_actx[bid * DENC + i];
            __syncthreads();
            int o = tid >> 1, hf = tid & 1;
            float s = 0.f;
            if (o < NMEL) {
                const float* wr = Wp + (size_t)o * 1536 + hf * 768;
                const float* xp = xin + hf * 768;
                for (int k = 0; k < 768; k++) s = fmaf(wr[k], xp[k], s);
            }
            s += __shfl_xor_sync(0xffffffffu, s, 1);
            if (o < NMEL && hf == 0)
                outs[((size_t)bid * TOUT + (t - 1)) * NMEL + o] = s + bp[o];
        }
        grid.sync();

        // ---- PB: attn gates ----
        gates_phase(b_a, d_ah, d_ac);
        grid.sync();

        // ---- PC1: pq + location conv + energies (4 blocks per batch) ----
        {
            int b = bid >> 2, q = bid & 3, pos0 = q * 50;
            float* aw_s   = pool;            // 200
            float* cum_s  = pool + 200;      // 200
            float* v_s    = pool + 400;      // 128
            float* pq_s   = pool + 528;      // 128
            float* Wloc_s = pool + 656;      // 4096
            float* locraw = pool + 4752;     // 1600
            for (int i = tid; i < 4096; i += NT) Wloc_s[i] = Wloc[i];
            if (tid < 128) v_s[tid] = v[tid];
            for (int i = tid; i < TIN; i += NT) {
                aw_s[i]  = d_aw[b * TIN + i];
                cum_s[i] = d_cum[b * TIN + i];
            }
            __syncthreads();
            // pq = Wq @ ah[b]
            {
                const float4* ah4 = (const float4*)(d_ah + b * DRNN);
                for (int a = wid * 16; a < wid * 16 + 16; a++) {
                    const float4* wr4 = (const float4*)(Wq + (size_t)a * DRNN);
                    float s = 0.f;
                    for (int k4 = lane; k4 < 256; k4 += 32) {
                        float4 w = wr4[k4]; float4 x = ah4[k4];
                        s = fmaf(w.x, x.x, s); s = fmaf(w.y, x.y, s);
                        s = fmaf(w.z, x.z, s); s = fmaf(w.w, x.w, s);
                    }
                    #pragma unroll
                    for (int o = 16; o > 0; o >>= 1) s += __shfl_xor_sync(0xffffffffu, s, o);
                    if (lane == 0) pq_s[a] = s;
                }
            }
            // conv for 50 local positions
            for (int o = tid; o < 32 * 50; o += NT) {
                int lp = o >> 5, f = o & 31;
                int ppos = pos0 + lp;
                const float* w0 = Wconv + f * 62;
                float a0 = 0.f;
                #pragma unroll
                for (int kk = 0; kk < KSZ; kk++) {
                    int ip = ppos + kk - 15;
                    if (ip >= 0 && ip < TIN)
                        a0 += aw_s[ip] * w0[kk] + cum_s[ip] * w0[31 + kk];
                }
                locraw[f * 50 + lp] = a0;
            }
            __syncthreads();
            // energies: 100 threads, pair per position (ATT split 64/64)
            int len_b = lens[b];
            int lp = tid >> 1, ahalf = tid & 1;
            int ppos = pos0 + lp;
            bool active = (tid < 100);
            float part = 0.f;
            if (active && ppos < len_b) {
                float lr[32];
                #pragma unroll
                for (int f = 0; f < 32; f++) lr[f] = locraw[f * 50 + lp];
                const float* pmrow = d_pmT + ((size_t)b * ATT + ahalf * 64) * TIN + ppos;
                const float* vv = v_s + ahalf * 64;
                const float* pqp = pq_s + ahalf * 64;
                const float* wl = Wloc_s + ahalf * 64 * 32;
                for (int a = 0; a < 64; a++) {
                    float lpv = pqp[a];
                    #pragma unroll
                    for (int f = 0; f < 32; f++)
                        lpv = fmaf(wl[a * 32 + f], lr[f], lpv);
                    part = fmaf(vv[a], tanh_fast(lpv + pmrow[(size_t)a * TIN]), part);
                }
            }
            part += __shfl_xor_sync(0xffffffffu, part, 1);
            if (active && ahalf == 0)
                d_e[b * TIN + ppos] = (ppos < len_b) ? part : -1.0e8f;
        }
        grid.sync();

        // ---- PC2: softmax (redundant x4) + context (column slice per block) ----
        {
            int b = bid >> 2, q = bid & 3;
            float* e_s  = pool;        // 200 (pad)
            float* red  = pool + 256;  // 256
            float* aw_s = pool + 512;  // 200 (pad)
            float* ctx  = pool + 768;  // 256
            for (int i = tid; i < TIN; i += NT) e_s[i] = d_e[b * TIN + i];
            __syncthreads();
            red[tid] = (tid < TIN) ? e_s[tid] : -3.402823466e38f;
            __syncthreads();
            for (int s = 128; s > 0; s >>= 1) {
                if (tid < s) red[tid] = fmaxf(red[tid], red[tid + s]);
                __syncthreads();
            }
            float mx = red[0];
            __syncthreads();
            float p = (tid < TIN) ? __expf(e_s[tid] - mx) : 0.f;
            red[tid] = p;
            __syncthreads();
            for (int s = 128; s > 0; s >>= 1) {
                if (tid < s) red[tid] += red[tid + s];
                __syncthreads();
            }
            float inv = __fdividef(1.0f, red[0]);
            __syncthreads();
            if (tid < TIN) {
                float awn = p * inv;
                aw_s[tid] = awn;
                if (q == 0) {
                    d_aw[b * TIN + tid]  = awn;
                    d_cum[b * TIN + tid] = d_cum[b * TIN + tid] + awn;
                    aligns[((size_t)b * TOUT + t) * TIN + tid] = awn;
                }
            }
            __syncthreads();
            // context: columns [q*128, q*128+128), positions split in 2 halves
            int col = tid & 127, half = tid >> 7;
            const float* ep = enc + ((size_t)b * TIN + half * 100) * DENC + q * 128 + col;
            float acc = 0.f;
            #pragma unroll 4
            for (int pz = 0; pz < 100; pz++)
                acc = fmaf(aw_s[half * 100 + pz], ep[(size_t)pz * DENC], acc);
            ctx[tid] = acc;
            __syncthreads();
            if (tid < 128)
                d_actx[b * DENC + q * 128 + tid] = ctx[tid] + ctx[128 + tid];
        }
        grid.sync();

        // ---- PD: dec GEMM ----
        gemm_phase(pool, Wih_d, 1536, Whh_d, d_ah, DRNN, d_dh, 2560 / KSPLIT, bid);
        grid.sync();

        // ---- PE: dec gates ----
        gates_phase(b_d, d_dh, d_dc);
        grid.sync();
    }

    // final output projection for t = TOUT-1
    if (bid < BB) {
        float* xin = pool;
        for (int i = tid; i < 1024; i += NT) xin[i] = d_dh[bid * DRNN + i];
        for (int i = tid; i < 512;  i += NT) xin[1024 + i] = d_actx[bid * DENC + i];
        __syncthreads();
        int o = tid >> 1, hf = tid & 1;
        float s = 0.f;
        if (o < NMEL) {
            const float* wr = Wp + (size_t)o * 1536 + hf * 768;
            const float* xp = xin + hf * 768;
            for (int k = 0; k < 768; k++) s = fmaf(wr[k], xp[k], s);
        }
        s += __shfl_xor_sync(0xffffffffu, s, 1);
        if (o < NMEL && hf == 0)
            outs[((size_t)bid * TOUT + (TOUT - 1)) * NMEL + o] = s + bp[o];
    }
}

// ---------------- launch ----------------
extern "C" void kernel_launch(void* const* d_in, const int* in_sizes, int n_in,
                              void* d_out, int out_size) {
    const float* enc   = (const float*)d_in[0];
    const float* dec   = (const float*)d_in[1];
    const int*   lens  = (const int*)  d_in[2];
    const float* Wp1   = (const float*)d_in[3];
    const float* Wp2   = (const float*)d_in[4];
    const float* Wih_a = (const float*)d_in[5];
    const float* Whh_a = (const float*)d_in[6];
    const float* b_a   = (const float*)d_in[7];
    const float* Wq    = (const float*)d_in[8];
    const float* Wmem  = (const float*)d_in[9];
    const float* v     = (const float*)d_in[10];
    const float* Wconv = (const float*)d_in[11];
    const float* Wloc  = (const float*)d_in[12];
    const float* Wih_d = (const float*)d_in[13];
    const float* Whh_d = (const float*)d_in[14];
    const float* b_d   = (const float*)d_in[15];
    const float* Wp    = (const float*)d_in[16];
    const float* bp    = (const float*)d_in[17];

    float* outs   = (float*)d_out;
    float* aligns = outs + (size_t)BB * TOUT * NMEL;

    init_state_kernel<<<64, 256>>>();
    prenet_kernel<<<dim3(TOUT, 2), 256>>>(dec, Wp1, Wp2);
    procmem_kernel<<<dim3(BB, TIN / 8), 128>>>(enc, Wmem);

    void* args[] = {
        (void*)&enc, (void*)&lens,
        (void*)&Wih_a, (void*)&Whh_a, (void*)&b_a,
        (void*)&Wq, (void*)&Wconv, (void*)&Wloc, (void*)&v,
        (void*)&Wih_d, (void*)&Whh_d, (void*)&b_d,
        (void*)&Wp, (void*)&bp,
        (void*)&outs, (void*)&aligns
    };
    cudaLaunchCooperativeKernel((void*)persistent_kernel,
                                dim3(NB), dim3(NT), args, 0, (cudaStream_t)0);
}

// round 6
// speedup vs baseline: 1.3280x; 1.3280x over previous
#include <cuda_runtime.h>
#include <cooperative_groups.h>
#include <cstdint>
#include <cstddef>

namespace cg = cooperative_groups;

#define BB      64
#define TIN     200
#define TOUT    400
#define DENC    512
#define DRNN    1024
#define PRE     256
#define ATT     128
#define KSZ     31
#define NMEL    80
#define GATESZ  4096
#define KSPLIT  8
#define NB      256
#define NT      256

// packed fp32x2 FMA (Blackwell FFMA2) — bit-identical to two scalar FFMAs
#define FMA2(d, a, b) asm("fma.rn.f32x2 %0, %1, %2, %0;" : "+l"(d) : "l"(a), "l"(b))

// ---------------- device scratch ----------------
__device__ float d_xs[(size_t)TOUT * BB * PRE];
__device__ float d_pmT[(size_t)BB * ATT * TIN];   // [b][a][t]
__device__ float d_ah[BB * DRNN];
__device__ float d_ac[BB * DRNN];
__device__ float d_dh[BB * DRNN];
__device__ float d_dc[BB * DRNN];
__device__ float d_aw[BB * TIN];
__device__ float d_cum[BB * TIN];
__device__ float d_actx[BB * DENC];
__device__ float d_gpart_a[(size_t)KSPLIT * GATESZ * BB];   // [s][b][m]
__device__ float d_gpart_d[(size_t)KSPLIT * GATESZ * BB];   // [s][b][m]

// ---------------- fast math ----------------
__device__ __forceinline__ float tanh_fast(float x) {
    float ax = fabsf(x);
    float t  = __expf(-2.0f * ax);
    float r  = __fdividef(1.0f - t, 1.0f + t);
    return copysignf(r, x);
}
__device__ __forceinline__ float sig_fast(float x) {
    return __fdividef(1.0f, 1.0f + __expf(-x));
}

// ---------------- init (runs every replay: determinism) ----------------
__global__ void init_state_kernel() {
    int i = blockIdx.x * 256 + threadIdx.x;
    int n = gridDim.x * 256;
    for (int k = i; k < BB * DRNN; k += n) { d_ah[k]=0.f; d_ac[k]=0.f; d_dh[k]=0.f; d_dc[k]=0.f; }
    for (int k = i; k < BB * TIN;  k += n) { d_aw[k]=0.f; d_cum[k]=0.f; }
    for (int k = i; k < BB * DENC; k += n) d_actx[k]=0.f;
}

// ---------------- prenet (all 400 steps, parallel) ----------------
__global__ void prenet_kernel(const float* __restrict__ dec_in,
                              const float* __restrict__ Wp1,
                              const float* __restrict__ Wp2) {
    __shared__ float di_s[32 * NMEL];
    __shared__ float h1_s[32 * PRE];
    int t = blockIdx.x, b0 = blockIdx.y * 32, tid = threadIdx.x;
    for (int i = tid; i < 32 * NMEL; i += 256) {
        int b = i / NMEL, k = i - b * NMEL;
        di_s[i] = (t == 0) ? 0.f : dec_in[((size_t)(t - 1) * BB + (b0 + b)) * NMEL + k];
    }
    __syncthreads();
    {
        const float* wr = Wp1 + tid * NMEL;
        for (int c = 0; c < 2; c++) {
            float acc[16];
            #pragma unroll
            for (int r = 0; r < 16; r++) acc[r] = 0.f;
            for (int k = 0; k < NMEL; k++) {
                float w = wr[k];
                #pragma unroll
                for (int r = 0; r < 16; r++)
                    acc[r] = fmaf(w, di_s[(c * 16 + r) * NMEL + k], acc[r]);
            }
            #pragma unroll
            for (int r = 0; r < 16; r++)
                h1_s[(c * 16 + r) * PRE + tid] = fmaxf(acc[r], 0.f);
        }
    }
    __syncthreads();
    {
        const float* wr = Wp2 + tid * PRE;
        for (int c = 0; c < 2; c++) {
            float acc[16];
            #pragma unroll
            for (int r = 0; r < 16; r++) acc[r] = 0.f;
            for (int k = 0; k < PRE; k++) {
                float w = wr[k];
                #pragma unroll
                for (int r = 0; r < 16; r++)
                    acc[r] = fmaf(w, h1_s[(c * 16 + r) * PRE + k], acc[r]);
            }
            #pragma unroll
            for (int r = 0; r < 16; r++)
                d_xs[((size_t)t * BB + (b0 + c * 16 + r)) * PRE + tid] = fmaxf(acc[r], 0.f);
        }
    }
}

// ---------------- processed memory, transposed: pmT[b][a][t] ----------------
__global__ void procmem_kernel(const float* __restrict__ enc,
                               const float* __restrict__ Wmem) {
    __shared__ float es[8 * DENC];
    int b = blockIdx.x, t0 = blockIdx.y * 8, tid = threadIdx.x;  // 128 threads
    for (int i = tid; i < 8 * DENC; i += 128)
        es[i] = enc[((size_t)b * TIN + t0) * DENC + i];
    __syncthreads();
    const float* wr = Wmem + tid * DENC;
    float acc[8];
    #pragma unroll
    for (int r = 0; r < 8; r++) acc[r] = 0.f;
    for (int e = 0; e < DENC; e++) {
        float w = wr[e];
        #pragma unroll
        for (int r = 0; r < 8; r++) acc[r] = fmaf(w, es[r * DENC + e], acc[r]);
    }
    #pragma unroll
    for (int r = 0; r < 8; r++)
        d_pmT[((size_t)b * ATT + tid) * TIN + t0 + r] = acc[r];
}

// ---------------- pipelined K-split GEMM with FFMA2 ----------------
// gpart[split][b][m] = sum_k W[m][k] * x[b][k]; tile 128m x 64b, chunk 32k
__device__ __forceinline__ void gemm_phase(
    float* pool,
    const float* __restrict__ Wih, int K1,
    const float* __restrict__ Whh,
    const float* __restrict__ x0, int L0,
    const float* __restrict__ x2,
    int Kq, int item, float* gpart_base) {
    float* Ws = pool;           // 32*132
    float* Xs = pool + 4224;    // 32*68
    const int tid = threadIdx.x;
    const int m0 = (item & 31) * 128;
    const int kstart = (item >> 5) * Kq;
    const int nch = Kq >> 5;
    const int tr = tid >> 3, tb = tid & 7;
    const int L01 = L0 + DENC;

    unsigned long long acc2[4][4];
    #pragma unroll
    for (int i = 0; i < 4; i++)
        #pragma unroll
        for (int p = 0; p < 4; p++) acc2[i][p] = 0ull;

    float wreg[16], xreg[8];
    {   // prologue load of chunk 0
        int kc = kstart;
        #pragma unroll
        for (int q = 0; q < 16; q++) {
            int idx = tid + q * 256, ml = idx >> 5, kg = kc + (idx & 31);
            wreg[q] = (kg < K1) ? Wih[(size_t)(m0 + ml) * K1 + kg]
                                : Whh[(size_t)(m0 + ml) * 1024 + (kg - K1)];
        }
        #pragma unroll
        for (int q = 0; q < 8; q++) {
            int idx = tid + q * 256, bl = idx >> 5, kg = kc + (idx & 31);
            xreg[q] = (kg < L0)  ? x0[bl * L0 + kg]
                    : (kg < L01) ? d_actx[bl * DENC + (kg - L0)]
                                 : x2[bl * 1024 + (kg - L01)];
        }
    }
    for (int c = 0; c < nch; c++) {
        #pragma unroll
        for (int q = 0; q < 16; q++) {
            int idx = tid + q * 256;
            Ws[(idx & 31) * 132 + (idx >> 5)] = wreg[q];
        }
        #pragma unroll
        for (int q = 0; q < 8; q++) {
            int idx = tid + q * 256;
            Xs[(idx & 31) * 68 + (idx >> 5)] = xreg[q];
        }
        if (c + 1 < nch) {      // prefetch next chunk (overlaps with compute)
            int kc = kstart + (c + 1) * 32;
            #pragma unroll
            for (int q = 0; q < 16; q++) {
                int idx = tid + q * 256, ml = idx >> 5, kg = kc + (idx & 31);
                wreg[q] = (kg < K1) ? Wih[(size_t)(m0 + ml) * K1 + kg]
                                    : Whh[(size_t)(m0 + ml) * 1024 + (kg - K1)];
            }
            #pragma unroll
            for (int q = 0; q < 8; q++) {
                int idx = tid + q * 256, bl = idx >> 5, kg = kc + (idx & 31);
                xreg[q] = (kg < L0)  ? x0[bl * L0 + kg]
                        : (kg < L01) ? d_actx[bl * DENC + (kg - L0)]
                                     : x2[bl * 1024 + (kg - L01)];
            }
        }
        __syncthreads();
        #pragma unroll
        for (int k = 0; k < 32; k++) {
            float4 w4 = *(const float4*)&Ws[k * 132 + tr * 4];
            ulonglong2 xa = *(const ulonglong2*)&Xs[k * 68 + tb * 8];
            ulonglong2 xb = *(const ulonglong2*)&Xs[k * 68 + tb * 8 + 4];
            unsigned long long xp0 = xa.x, xp1 = xa.y, xp2 = xb.x, xp3 = xb.y;
            float wv[4] = {w4.x, w4.y, w4.z, w4.w};
            #pragma unroll
            for (int i = 0; i < 4; i++) {
                unsigned long long w2;
                unsigned wu = __float_as_uint(wv[i]);
                asm("mov.b64 %0, {%1, %1};" : "=l"(w2) : "r"(wu));
                FMA2(acc2[i][0], w2, xp0);
                FMA2(acc2[i][1], w2, xp1);
                FMA2(acc2[i][2], w2, xp2);
                FMA2(acc2[i][3], w2, xp3);
            }
        }
        __syncthreads();
    }
    float* gp = gpart_base + (size_t)(item >> 5) * (GATESZ * BB);
    #pragma unroll
    for (int p = 0; p < 4; p++) {
        float lo[4], hi[4];
        #pragma unroll
        for (int i = 0; i < 4; i++) {
            float2 f = *(float2*)&acc2[i][p];
            lo[i] = f.x; hi[i] = f.y;
        }
        int b0 = tb * 8 + 2 * p;
        *(float4*)&gp[(size_t)b0 * GATESZ + m0 + tr * 4] =
            make_float4(lo[0], lo[1], lo[2], lo[3]);
        *(float4*)&gp[(size_t)(b0 + 1) * GATESZ + m0 + tr * 4] =
            make_float4(hi[0], hi[1], hi[2], hi[3]);
    }
}

// ---------------- per-batch LSTM gates (block-local, coalesced) ----------------
__device__ __forceinline__ void gates_batch(const float* __restrict__ bias, int b,
                                            const float* __restrict__ gpart_base,
                                            float* __restrict__ hg,
                                            float* __restrict__ cg,
                                            float* hs) {
    int tid = threadIdx.x;
    #pragma unroll
    for (int r = 0; r < 4; r++) {
        int j = tid + 256 * r;
        float gi = bias[j], gf = bias[j + 1024], gg = bias[j + 2048], go = bias[j + 3072];
        #pragma unroll
        for (int s = 0; s < KSPLIT; s++) {
            const float* gp = gpart_base + (size_t)s * (GATESZ * BB) + (size_t)b * GATESZ;
            gi += gp[j]; gf += gp[j + 1024]; gg += gp[j + 2048]; go += gp[j + 3072];
        }
        float cn = sig_fast(gf) * cg[b * DRNN + j] + sig_fast(gi) * tanh_fast(gg);
        cg[b * DRNN + j] = cn;
        float hn = sig_fast(go) * tanh_fast(cn);
        hg[b * DRNN + j] = hn;
        if (hs) hs[j] = hn;
    }
}

// ---------------- dec gates + output projection for step t_prev ----------------
__device__ __forceinline__ void decgates_out(float* pool, const float* __restrict__ b_d,
                                             const float* __restrict__ Wp,
                                             const float* __restrict__ bp,
                                             float* __restrict__ outs, int b, int t_prev) {
    int tid = threadIdx.x;
    float* xin = pool;   // 1536
    gates_batch(b_d, b, d_gpart_d, d_dh, d_dc, xin);
    for (int i = tid; i < 512; i += 256) xin[1024 + i] = d_actx[b * DENC + i];
    __syncthreads();
    int o = tid >> 1, hf = tid & 1;
    float s = 0.f;
    if (o < NMEL) {
        const float4* wr4 = (const float4*)(Wp + (size_t)o * 1536 + hf * 768);
        const float4* xp4 = (const float4*)(xin + hf * 768);
        for (int k = 0; k < 192; k++) {
            float4 w = wr4[k], x = xp4[k];
            s = fmaf(w.x, x.x, s); s = fmaf(w.y, x.y, s);
            s = fmaf(w.z, x.z, s); s = fmaf(w.w, x.w, s);
        }
    }
    s += __shfl_xor_sync(0xffffffffu, s, 1);
    if (o < NMEL && hf == 0)
        outs[((size_t)b * TOUT + t_prev) * NMEL + o] = s + bp[o];
    __syncthreads();
}

// ---------------- persistent kernel: 3 grid.syncs per step ----------------
__global__ void __launch_bounds__(NT, 2)
persistent_kernel(const float* __restrict__ enc, const int* __restrict__ lens,
                  const float* __restrict__ Wih_a, const float* __restrict__ Whh_a,
                  const float* __restrict__ b_a,
                  const float* __restrict__ Wq, const float* __restrict__ Wconv,
                  const float* __restrict__ Wloc, const float* __restrict__ v,
                  const float* __restrict__ Wih_d, const float* __restrict__ Whh_d,
                  const float* __restrict__ b_d,
                  const float* __restrict__ Wp, const float* __restrict__ bp,
                  float* __restrict__ outs, float* __restrict__ aligns) {
    cg::grid_group grid = cg::this_grid();
    __shared__ __align__(16) float pool[8032];
    const int bid = blockIdx.x, tid = threadIdx.x;
    const int wid = tid >> 5, lane = tid & 31;

    for (int t = 0; t < TOUT; t++) {
        // ---- PA: dec-gates(t-1)+out(t-1) on blocks<64; attn GEMM on all ----
        if (t > 0 && bid < BB)
            decgates_out(pool, b_d, Wp, bp, outs, bid, t - 1);
        gemm_phase(pool, Wih_a, 768, Whh_a,
                   d_xs + (size_t)t * BB * PRE, PRE, d_ah,
                   1792 / KSPLIT, bid, d_gpart_a);
        grid.sync();

        // ---- PC: attn gates + pq + conv + energies + softmax + context ----
        if (bid < BB) {
            const int b = bid;
            float* ah_s   = pool;            // 1024
            float* aw_s   = pool + 1024;     // 200
            float* cum_s  = pool + 1224;     // 200
            float* v_s    = pool + 1424;     // 128
            float* pq_s   = pool + 1552;     // 128
            float* red    = pool + 1680;     // 256
            float* Wc_s   = pool + 1936;     // 1984
            float* Wloc_s = pool + 3920;     // 4096 -> ends 8016

            for (int i = tid; i < 4096; i += NT) Wloc_s[i] = Wloc[i];
            for (int i = tid; i < 1984; i += NT) Wc_s[i] = Wconv[i];
            if (tid < 128) v_s[tid] = v[tid];
            for (int i = tid; i < TIN; i += NT) {
                aw_s[i]  = d_aw[b * TIN + i];
                cum_s[i] = d_cum[b * TIN + i];
            }
            gates_batch(b_a, b, d_gpart_a, d_ah, d_ac, ah_s);
            __syncthreads();

            // pq = Wq @ ah
            {
                const float4* ah4 = (const float4*)ah_s;
                for (int a = wid * 16; a < wid * 16 + 16; a++) {
                    const float4* wr4 = (const float4*)(Wq + (size_t)a * DRNN);
                    float s = 0.f;
                    for (int k4 = lane; k4 < 256; k4 += 32) {
                        float4 w = wr4[k4]; float4 x = ah4[k4];
                        s = fmaf(w.x, x.x, s); s = fmaf(w.y, x.y, s);
                        s = fmaf(w.z, x.z, s); s = fmaf(w.w, x.w, s);
                    }
                    #pragma unroll
                    for (int o = 16; o > 0; o >>= 1) s += __shfl_xor_sync(0xffffffffu, s, o);
                    if (lane == 0) pq_s[a] = s;
                }
            }
            __syncthreads();

            // conv (per-position, in registers) + energies
            float e = -3.402823466e38f;
            int len_b = lens[b];
            if (tid < TIN) {
                if (tid >= len_b) e = -1.0e8f;
                else {
                    float lr[32];
                    #pragma unroll
                    for (int f = 0; f < 32; f++) {
                        const float* w0 = Wc_s + f * 62;
                        float a0 = 0.f;
                        #pragma unroll
                        for (int kk = 0; kk < KSZ; kk++) {
                            int ip = tid + kk - 15;
                            if (ip >= 0 && ip < TIN)
                                a0 += aw_s[ip] * w0[kk] + cum_s[ip] * w0[31 + kk];
                        }
                        lr[f] = a0;
                    }
                    const float* pmrow = d_pmT + (size_t)b * ATT * TIN + tid;
                    float acc = 0.f;
                    for (int a = 0; a < ATT; a++) {
                        float lp = pq_s[a];
                        #pragma unroll
                        for (int f = 0; f < 32; f++)
                            lp = fmaf(Wloc_s[a * 32 + f], lr[f], lp);
                        acc = fmaf(v_s[a], tanh_fast(lp + pmrow[(size_t)a * TIN]), acc);
                    }
                    e = acc;
                }
            }
            red[tid] = e;
            __syncthreads();
            for (int s = 128; s > 0; s >>= 1) {
                if (tid < s) red[tid] = fmaxf(red[tid], red[tid + s]);
                __syncthreads();
            }
            float mx = red[0];
            __syncthreads();
            float p = (tid < TIN) ? __expf(e - mx) : 0.f;
            red[tid] = p;
            __syncthreads();
            for (int s = 128; s > 0; s >>= 1) {
                if (tid < s) red[tid] += red[tid + s];
                __syncthreads();
            }
            float inv = __fdividef(1.0f, red[0]);
            __syncthreads();
            if (tid < TIN) {
                float awn = p * inv;
                aw_s[tid] = awn;
                d_aw[b * TIN + tid]  = awn;
                d_cum[b * TIN + tid] = cum_s[tid] + awn;
                aligns[((size_t)b * TOUT + t) * TIN + tid] = awn;
            }
            __syncthreads();
            // context: 2 columns per thread
            const float* ep = enc + (size_t)b * TIN * DENC;
            float acc0 = 0.f, acc1 = 0.f;
            #pragma unroll 4
            for (int pos = 0; pos < TIN; pos++) {
                float w = aw_s[pos];
                acc0 = fmaf(w, ep[(size_t)pos * DENC + tid], acc0);
                acc1 = fmaf(w, ep[(size_t)pos * DENC + tid + 256], acc1);
            }
            d_actx[b * DENC + tid]       = acc0;
            d_actx[b * DENC + tid + 256] = acc1;
        }
        grid.sync();

        // ---- PD: dec GEMM ----
        gemm_phase(pool, Wih_d, 1536, Whh_d, d_ah, 1024, d_dh,
                   2560 / KSPLIT, bid, d_gpart_d);
        grid.sync();
    }

    // epilogue: final dec gates + out(t = TOUT-1)
    if (bid < BB)
        decgates_out(pool, b_d, Wp, bp, outs, bid, TOUT - 1);
}

// ---------------- launch ----------------
extern "C" void kernel_launch(void* const* d_in, const int* in_sizes, int n_in,
                              void* d_out, int out_size) {
    const float* enc   = (const float*)d_in[0];
    const float* dec   = (const float*)d_in[1];
    const int*   lens  = (const int*)  d_in[2];
    const float* Wp1   = (const float*)d_in[3];
    const float* Wp2   = (const float*)d_in[4];
    const float* Wih_a = (const float*)d_in[5];
    const float* Whh_a = (const float*)d_in[6];
    const float* b_a   = (const float*)d_in[7];
    const float* Wq    = (const float*)d_in[8];
    const float* Wmem  = (const float*)d_in[9];
    const float* v     = (const float*)d_in[10];
    const float* Wconv = (const float*)d_in[11];
    const float* Wloc  = (const float*)d_in[12];
    const float* Wih_d = (const float*)d_in[13];
    const float* Whh_d = (const float*)d_in[14];
    const float* b_d   = (const float*)d_in[15];
    const float* Wp    = (const float*)d_in[16];
    const float* bp    = (const float*)d_in[17];

    float* outs   = (float*)d_out;
    float* aligns = outs + (size_t)BB * TOUT * NMEL;

    init_state_kernel<<<64, 256>>>();
    prenet_kernel<<<dim3(TOUT, 2), 256>>>(dec, Wp1, Wp2);
    procmem_kernel<<<dim3(BB, TIN / 8), 128>>>(enc, Wmem);

    void* args[] = {
        (void*)&enc, (void*)&lens,
        (void*)&Wih_a, (void*)&Whh_a, (void*)&b_a,
        (void*)&Wq, (void*)&Wconv, (void*)&Wloc, (void*)&v,
        (void*)&Wih_d, (void*)&Whh_d, (void*)&b_d,
        (void*)&Wp, (void*)&bp,
        (void*)&outs, (void*)&aligns
    };
    cudaLaunchCooperativeKernel((void*)persistent_kernel,
                                dim3(NB), dim3(NT), args, 0, (cudaStream_t)0);
}